// round 5
// baseline (speedup 1.0000x reference)
#include <cuda_runtime.h>
#include <math.h>

#define LAYERS 8
#define H      1024
#define NH     16
#define KVH    4
#define HD     64
#define INTER  2816
#define VOCAB  32000
#define CTX    2048
#define EPS    1e-5f

#define NBLOCKS 148
#define NWARPS  (NBLOCKS * 32)
#define ACHUNKS 8           // attention position chunks per head

// ---------------------------------------------------------------------------
// global scratch (allocation-free)
__device__ __align__(16) float g_hA[H];
__device__ __align__(16) float g_hB[H];
__device__ __align__(16) float g_qkvp[2][H + 2 * KVH * HD];   // qkv split-2 partials
__device__ __align__(16) float g_op[4][H];                    // o-proj partials
__device__ __align__(16) float g_gp[2][INTER];                // gate partials
__device__ __align__(16) float g_upp[2][INTER];               // up partials
__device__ __align__(16) float g_dp[4][H];                    // down partials
__device__ float g_am[NH][ACHUNKS];                           // chunk max
__device__ float g_as[NH][ACHUNKS];                           // chunk expsum
__device__ __align__(16) float g_ao[NH][ACHUNKS][HD];         // chunk sum(e*v)
__device__ float    g_lmv[NBLOCKS];
__device__ int      g_lmi[NBLOCKS];
// tree barrier state: per-block generation flags + global generation
__device__ volatile unsigned g_flags[NBLOCKS];
__device__ volatile unsigned g_gen;

// ---------------------------------------------------------------------------
// Tree grid sync: no atomic contention. Each call increments the caller's
// local generation counter `gen` (all threads keep identical copies).
__device__ __forceinline__ void grid_sync(unsigned& gen, int bid) {
    gen++;
    __syncthreads();
    if (threadIdx.x < 32) {
        if (threadIdx.x == 0) {
            __threadfence();                 // publish this block's writes
            g_flags[bid] = gen;              // plain store, distinct address
        }
        if (bid == 0) {
            // warp 0 of block 0 gathers all flags (5 per lane)
            bool ok;
            do {
                ok = true;
                #pragma unroll
                for (int i = threadIdx.x; i < NBLOCKS; i += 32)
                    if ((int)(g_flags[i] - gen) < 0) ok = false;
            } while (!__all_sync(~0u, ok));
            if (threadIdx.x == 0) {
                __threadfence();
                g_gen = gen;                 // release to everyone
            }
        } else if (threadIdx.x == 0) {
            while ((int)(g_gen - gen) < 0) { }
            __threadfence();                 // acquire: invalidate L1
        }
    }
    __syncthreads();
}

// block sum over 1024 threads (returns to all threads)
__device__ __forceinline__ float block_rsum(float v, float* red) {
    int lane = threadIdx.x & 31, wid = threadIdx.x >> 5;
    #pragma unroll
    for (int o = 16; o; o >>= 1) v += __shfl_xor_sync(~0u, v, o);
    if (lane == 0) red[wid] = v;
    __syncthreads();
    if (threadIdx.x == 0) {
        float t = 0.f;
        #pragma unroll
        for (int i = 0; i < 32; i++) t += red[i];
        red[0] = t;
    }
    __syncthreads();
    float r = red[0];
    __syncthreads();
    return r;
}

__device__ __forceinline__ float block_rmax(float v, float* red) {
    int lane = threadIdx.x & 31, wid = threadIdx.x >> 5;
    #pragma unroll
    for (int o = 16; o; o >>= 1) v = fmaxf(v, __shfl_xor_sync(~0u, v, o));
    if (lane == 0) red[wid] = v;
    __syncthreads();
    if (threadIdx.x == 0) {
        float t = red[0];
        #pragma unroll
        for (int i = 1; i < 32; i++) t = fmaxf(t, red[i]);
        red[0] = t;
    }
    __syncthreads();
    float r = red[0];
    __syncthreads();
    return r;
}

// ---------------------------------------------------------------------------
__global__ void __launch_bounds__(1024, 1)
decode_k(const float* __restrict__ embed,  const float* __restrict__ q_w,
         const float* __restrict__ k_w,    const float* __restrict__ v_w,
         const float* __restrict__ o_w,    const float* __restrict__ gate_w,
         const float* __restrict__ up_w,   const float* __restrict__ down_w,
         const float* __restrict__ ln1_w,  const float* __restrict__ ln2_w,
         const float* __restrict__ norm_w, const float* __restrict__ lm_head,
         const float* __restrict__ kv,     const float* __restrict__ cosc,
         const float* __restrict__ sinc,   const int* __restrict__ input_ids,
         const int* __restrict__ pos_ids,  float* __restrict__ out) {
    __shared__ __align__(16) float xs[H];       // normed hidden / att operand
    __shared__ __align__(16) float xm[INTER];   // MLP activation operand
    __shared__ __align__(16) float sc[256];     // attention chunk scores
    __shared__ __align__(16) float part[32][HD];
    __shared__ __align__(16) float qs[HD], kn[HD], vn[HD];
    __shared__ float red[32];
    __shared__ int   redi[32];

    const int tid = threadIdx.x, lane = tid & 31, wid = tid >> 5;
    const int bid = blockIdx.x;
    const int gwarp = bid * 32 + wid;
    unsigned gen = 0;

    // ---- embed + zero first-layer down partials ----
    if (bid == 0) g_hA[tid] = embed[(size_t)input_ids[0] * H + tid];
    if (bid == 1) {
        #pragma unroll
        for (int s = 0; s < 4; s++) g_dp[s][tid] = 0.f;
    }
    grid_sync(gen, bid);

    const int pos = pos_ids[0];
    const int cl = (pos + ACHUNKS) >> 3;   // ceil((pos+1)/8)

    for (int l = 0; l < LAYERS; l++) {
        // =========== S1: combine h, rms1, qkv partials ===========
        float hv = g_hA[tid] + g_dp[0][tid] + g_dp[1][tid] + g_dp[2][tid] + g_dp[3][tid];
        if (bid == 0) g_hB[tid] = hv;
        xs[tid] = hv * ln1_w[(size_t)l * H + tid];
        float ssq = block_rsum(hv * hv, red);
        float rs = rsqrtf(ssq / (float)H + EPS);

        if (gwarp < 2 * (H + 2 * KVH * HD)) {           // 3072 units
            int row = gwarp >> 1, s2 = gwarp & 1;
            const float* W;
            if (row < H)
                W = q_w + (size_t)l * H * H + (size_t)row * H;
            else if (row < H + KVH * HD)
                W = k_w + (size_t)l * (KVH * HD) * H + (size_t)(row - H) * H;
            else
                W = v_w + (size_t)l * (KVH * HD) * H + (size_t)(row - H - KVH * HD) * H;
            const float4* w4 = (const float4*)W;
            const float4* x4 = (const float4*)xs;
            float s = 0.f;
            #pragma unroll
            for (int k = 0; k < 4; k++) {
                int i = s2 * 128 + lane + k * 32;
                float4 w = w4[i], a = x4[i];
                s += w.x * a.x + w.y * a.y + w.z * a.z + w.w * a.w;
            }
            #pragma unroll
            for (int o = 16; o; o >>= 1) s += __shfl_xor_sync(~0u, s, o);
            if (lane == 0) g_qkvp[s2][row] = s * rs;
        }
        grid_sync(gen, bid);

        // =========== S2: attention (flash-decode, 128 blocks) ===========
        if (bid < NH * ACHUNKS) {
            int head = bid >> 3, ch = bid & (ACHUNKS - 1), kvh = head >> 2;
            int j0 = ch * cl;
            int j1 = min(j0 + cl, pos + 1);
            int n = j1 - j0;

            if (tid < HD) {
                float c  = cosc[(size_t)pos * HD + tid];
                float sn = sinc[(size_t)pos * HD + tid];
                int qi = head * HD + tid;
                float q0 = g_qkvp[0][qi] + g_qkvp[1][qi];
                int qr_i = head * HD + ((tid < HD / 2) ? tid + HD / 2 : tid - HD / 2);
                float qr = g_qkvp[0][qr_i] + g_qkvp[1][qr_i];
                if (tid < HD / 2) qr = -qr;
                qs[tid] = q0 * c + qr * sn;

                int ki = H + kvh * HD + tid;
                float k0 = g_qkvp[0][ki] + g_qkvp[1][ki];
                int kr_i = H + kvh * HD + ((tid < HD / 2) ? tid + HD / 2 : tid - HD / 2);
                float kr = g_qkvp[0][kr_i] + g_qkvp[1][kr_i];
                if (tid < HD / 2) kr = -kr;
                kn[tid] = k0 * c + kr * sn;

                int vi = H + KVH * HD + kvh * HD + tid;
                vn[tid] = g_qkvp[0][vi] + g_qkvp[1][vi];
            }
            __syncthreads();

            const float* K = kv + (size_t)l * KVH * CTX * HD + (size_t)kvh * CTX * HD;
            const float* V = kv + (size_t)(LAYERS + l) * KVH * CTX * HD + (size_t)kvh * CTX * HD;
            const float4* q4 = (const float4*)qs;

            // scores: half-warp per row, warp-uniform bound, tail predicated
            int half = lane >> 4, hl = lane & 15;
            for (int jb = j0 + wid * 2; jb < j1; jb += 64) {
                int j = jb + half;
                bool valid = (j < j1);
                const float4* k4;
                if (!valid)           k4 = (const float4*)kn;
                else if (j == pos)    k4 = (const float4*)kn;
                else                  k4 = (const float4*)(K + (size_t)j * HD);
                float4 a = q4[hl], b = k4[hl];
                float s = a.x * b.x + a.y * b.y + a.z * b.z + a.w * b.w;
                #pragma unroll
                for (int o = 8; o; o >>= 1) s += __shfl_xor_sync(~0u, s, o);
                if (hl == 0 && valid) sc[j - j0] = s * 0.125f;
            }
            __syncthreads();

            float m = -1e30f;
            if (tid < n) m = sc[tid];
            float M = block_rmax(m, red);

            float e = 0.f;
            if (tid < n) {
                e = __expf(sc[tid] - M);
                sc[tid] = e;
            }
            float S = block_rsum(e, red);

            // AV: warps stride positions, lanes own 2 dims
            float a0 = 0.f, a1 = 0.f;
            for (int j = j0 + wid; j < j1; j += 32) {
                float p = sc[j - j0];
                const float* Vr = (j == pos) ? (const float*)vn : V + (size_t)j * HD;
                a0 += p * Vr[lane];
                a1 += p * Vr[lane + 32];
            }
            part[wid][lane]      = a0;
            part[wid][lane + 32] = a1;
            __syncthreads();
            if (tid == 0) { g_am[head][ch] = (n > 0) ? M : -1e30f; g_as[head][ch] = S; }
            if (tid < HD) {
                float t = 0.f;
                #pragma unroll
                for (int w = 0; w < 32; w++) t += part[w][tid];
                g_ao[head][ch][tid] = t;
            }
        }
        grid_sync(gen, bid);

        // =========== S3: combine attention, o-proj partials ===========
        {
            int head = tid >> 6, d = tid & (HD - 1);
            float M = -1e30f;
            #pragma unroll
            for (int c = 0; c < ACHUNKS; c++) M = fmaxf(M, g_am[head][c]);
            float S = 0.f, o = 0.f;
            #pragma unroll
            for (int c = 0; c < ACHUNKS; c++) {
                float e = __expf(g_am[head][c] - M);
                S += g_as[head][c] * e;
                o += g_ao[head][c][d] * e;
            }
            xs[tid] = o / S;
        }
        __syncthreads();

        if (gwarp < 4 * H) {                            // 4096 units
            int row = gwarp >> 2, s4 = gwarp & 3;
            const float4* w4 = (const float4*)(o_w + (size_t)l * H * H + (size_t)row * H);
            const float4* x4 = (const float4*)xs;
            float s = 0.f;
            #pragma unroll
            for (int k = 0; k < 2; k++) {
                int i = s4 * 64 + lane + k * 32;
                float4 w = w4[i], a = x4[i];
                s += w.x * a.x + w.y * a.y + w.z * a.z + w.w * a.w;
            }
            #pragma unroll
            for (int o = 16; o; o >>= 1) s += __shfl_xor_sync(~0u, s, o);
            if (lane == 0) g_op[s4][row] = s;
        }
        grid_sync(gen, bid);

        // =========== S4: combine h, rms2, gate+up partials ===========
        hv = g_hB[tid] + g_op[0][tid] + g_op[1][tid] + g_op[2][tid] + g_op[3][tid];
        if (bid == 0) g_hA[tid] = hv;
        xs[tid] = hv * ln2_w[(size_t)l * H + tid];
        ssq = block_rsum(hv * hv, red);
        rs = rsqrtf(ssq / (float)H + EPS);

        for (int u = gwarp; u < 2 * INTER; u += NWARPS) {   // 5632 units
            int r = u >> 1, s2 = u & 1;
            const float4* Wg = (const float4*)(gate_w + (size_t)l * INTER * H + (size_t)r * H);
            const float4* Wu = (const float4*)(up_w   + (size_t)l * INTER * H + (size_t)r * H);
            const float4* x4 = (const float4*)xs;
            float sg = 0.f, su = 0.f;
            #pragma unroll
            for (int k = 0; k < 4; k++) {
                int i = s2 * 128 + lane + k * 32;
                float4 wg = Wg[i], wu = Wu[i], a = x4[i];
                sg += wg.x * a.x + wg.y * a.y + wg.z * a.z + wg.w * a.w;
                su += wu.x * a.x + wu.y * a.y + wu.z * a.z + wu.w * a.w;
            }
            #pragma unroll
            for (int o = 16; o; o >>= 1) {
                sg += __shfl_xor_sync(~0u, sg, o);
                su += __shfl_xor_sync(~0u, su, o);
            }
            if (lane == 0) { g_gp[s2][r] = sg * rs; g_upp[s2][r] = su * rs; }
        }
        grid_sync(gen, bid);

        // =========== S5: combine gact -> smem, down partials ===========
        for (int i = tid; i < INTER; i += 1024) {
            float g = g_gp[0][i] + g_gp[1][i];
            float u = g_upp[0][i] + g_upp[1][i];
            xm[i] = (g / (1.f + __expf(-g))) * u;
        }
        __syncthreads();

        if (gwarp < 4 * H) {                            // 4096 units, 704 cols each
            int row = gwarp >> 2, s4 = gwarp & 3;
            const float4* w4 = (const float4*)(down_w + (size_t)l * H * INTER
                                               + (size_t)row * INTER + (size_t)s4 * 704);
            const float4* x4 = (const float4*)(xm + s4 * 704);
            float s = 0.f;
            for (int i = lane; i < 176; i += 32) {
                float4 w = w4[i], a = x4[i];
                s += w.x * a.x + w.y * a.y + w.z * a.z + w.w * a.w;
            }
            #pragma unroll
            for (int o = 16; o; o >>= 1) s += __shfl_xor_sync(~0u, s, o);
            if (lane == 0) g_dp[s4][row] = s;
        }
        grid_sync(gen, bid);
    }

    // =========== final norm + lm_head + argmax ===========
    float hv = g_hA[tid] + g_dp[0][tid] + g_dp[1][tid] + g_dp[2][tid] + g_dp[3][tid];
    xs[tid] = hv * norm_w[tid];
    float ssq = block_rsum(hv * hv, red);
    float rsf = rsqrtf(ssq / (float)H + EPS);

    float bv = -1e30f;
    int   bi = 0x7fffffff;
    for (int r = gwarp; r < VOCAB; r += NWARPS) {
        const float4* w4 = (const float4*)(lm_head + (size_t)r * H);
        const float4* x4 = (const float4*)xs;
        float s = 0.f;
        #pragma unroll
        for (int k = 0; k < 8; k++) {
            int i = lane + k * 32;
            float4 w = w4[i], a = x4[i];
            s += w.x * a.x + w.y * a.y + w.z * a.z + w.w * a.w;
        }
        #pragma unroll
        for (int o = 16; o; o >>= 1) s += __shfl_xor_sync(~0u, s, o);
        s *= rsf;
        if (s > bv) { bv = s; bi = r; }
    }
    if (lane == 0) { red[wid] = bv; redi[wid] = bi; }
    __syncthreads();
    if (tid == 0) {
        float b = red[0]; int ii = redi[0];
        #pragma unroll
        for (int i = 1; i < 32; i++)
            if (red[i] > b || (red[i] == b && redi[i] < ii)) { b = red[i]; ii = redi[i]; }
        g_lmv[bid] = b;
        g_lmi[bid] = ii;
    }
    grid_sync(gen, bid);
    if (bid == 0 && tid == 0) {
        float b = g_lmv[0]; int ii = g_lmi[0];
        for (int i = 1; i < NBLOCKS; i++) {
            float v = g_lmv[i]; int id = g_lmi[i];
            if (v > b || (v == b && id < ii)) { b = v; ii = id; }
        }
        out[0] = (float)ii;
        out[1] = b;
    }
}

// ---------------------------------------------------------------------------
extern "C" void kernel_launch(void* const* d_in, const int* in_sizes, int n_in,
                              void* d_out, int out_size) {
    const float* embed   = (const float*)d_in[0];
    const float* q_w     = (const float*)d_in[1];
    const float* k_w     = (const float*)d_in[2];
    const float* v_w     = (const float*)d_in[3];
    const float* o_w     = (const float*)d_in[4];
    const float* gate_w  = (const float*)d_in[5];
    const float* up_w    = (const float*)d_in[6];
    const float* down_w  = (const float*)d_in[7];
    const float* ln1_w   = (const float*)d_in[8];
    const float* ln2_w   = (const float*)d_in[9];
    const float* norm_w  = (const float*)d_in[10];
    const float* lm_head = (const float*)d_in[11];
    const float* kv      = (const float*)d_in[12];
    const float* cosc    = (const float*)d_in[13];
    const float* sinc    = (const float*)d_in[14];
    const int* input_ids = (const int*)d_in[17];
    const int* pos_ids   = (const int*)d_in[18];

    decode_k<<<NBLOCKS, 1024>>>(embed, q_w, k_w, v_w, o_w, gate_w, up_w, down_w,
                                ln1_w, ln2_w, norm_w, lm_head, kv, cosc, sinc,
                                input_ids, pos_ids, (float*)d_out);
}

// round 6
// speedup vs baseline: 1.0631x; 1.0631x over previous
#include <cuda_runtime.h>
#include <math.h>

#define LAYERS 8
#define H      1024
#define NH     16
#define KVH    4
#define HD     64
#define INTER  2816
#define VOCAB  32000
#define CTX    2048
#define EPS    1e-5f

#define NBLOCKS 148
#define NWARPS  (NBLOCKS * 32)
#define ACHUNKS 8           // attention position chunks per head

// ---------------------------------------------------------------------------
// global scratch (allocation-free)
__device__ __align__(16) float g_hA[H];
__device__ __align__(16) float g_hB[H];
__device__ __align__(16) float g_qkvp[2][H + 2 * KVH * HD];   // qkv split-2 partials
__device__ __align__(16) float g_op[4][H];                    // o-proj partials
__device__ __align__(16) float g_gp[2][INTER];                // gate partials
__device__ __align__(16) float g_upp[2][INTER];               // up partials
__device__ __align__(16) float g_dp[4][H];                    // down partials
__device__ float g_am[NH][ACHUNKS];
__device__ float g_as[NH][ACHUNKS];
__device__ __align__(16) float g_ao[NH][ACHUNKS][HD];
__device__ float    g_lmv[NBLOCKS];
__device__ int      g_lmi[NBLOCKS];
__device__ unsigned g_barcnt;
__device__ unsigned g_bargen;

// ---------------------------------------------------------------------------
// atomic grid barrier (R4-proven)
__device__ __forceinline__ void grid_sync() {
    __syncthreads();
    if (threadIdx.x == 0) {
        __threadfence();
        unsigned gen = *(volatile unsigned*)&g_bargen;
        if (atomicAdd(&g_barcnt, 1u) == NBLOCKS - 1) {
            g_barcnt = 0;
            __threadfence();
            atomicAdd(&g_bargen, 1u);
        } else {
            while (*(volatile unsigned*)&g_bargen == gen) { }
            __threadfence();
        }
    }
    __syncthreads();
}

__device__ __forceinline__ float block_rsum(float v, float* red) {
    int lane = threadIdx.x & 31, wid = threadIdx.x >> 5;
    #pragma unroll
    for (int o = 16; o; o >>= 1) v += __shfl_xor_sync(~0u, v, o);
    if (lane == 0) red[wid] = v;
    __syncthreads();
    if (threadIdx.x == 0) {
        float t = 0.f;
        #pragma unroll
        for (int i = 0; i < 32; i++) t += red[i];
        red[0] = t;
    }
    __syncthreads();
    float r = red[0];
    __syncthreads();
    return r;
}

__device__ __forceinline__ float block_rmax(float v, float* red) {
    int lane = threadIdx.x & 31, wid = threadIdx.x >> 5;
    #pragma unroll
    for (int o = 16; o; o >>= 1) v = fmaxf(v, __shfl_xor_sync(~0u, v, o));
    if (lane == 0) red[wid] = v;
    __syncthreads();
    if (threadIdx.x == 0) {
        float t = red[0];
        #pragma unroll
        for (int i = 1; i < 32; i++) t = fmaxf(t, red[i]);
        red[0] = t;
    }
    __syncthreads();
    float r = red[0];
    __syncthreads();
    return r;
}

__device__ __forceinline__ float d4(float4 w, float4 a) {
    return w.x * a.x + w.y * a.y + w.z * a.z + w.w * a.w;
}

// ---------------------------------------------------------------------------
__global__ void __launch_bounds__(1024, 1)
decode_k(const float* __restrict__ embed,  const float* __restrict__ q_w,
         const float* __restrict__ k_w,    const float* __restrict__ v_w,
         const float* __restrict__ o_w,    const float* __restrict__ gate_w,
         const float* __restrict__ up_w,   const float* __restrict__ down_w,
         const float* __restrict__ ln1_w,  const float* __restrict__ ln2_w,
         const float* __restrict__ norm_w, const float* __restrict__ lm_head,
         const float* __restrict__ kv,     const float* __restrict__ cosc,
         const float* __restrict__ sinc,   const int* __restrict__ input_ids,
         const int* __restrict__ pos_ids,  float* __restrict__ out) {
    __shared__ __align__(16) float xs[H];
    __shared__ __align__(16) float xm[INTER];
    __shared__ __align__(16) float sc[256];
    __shared__ __align__(16) float part[32][HD];
    __shared__ __align__(16) float qs[HD], kn[HD], vn[HD];
    __shared__ float red[32];
    __shared__ int   redi[32];

    const int tid = threadIdx.x, lane = tid & 31, wid = tid >> 5;
    const int bid = blockIdx.x;
    const int gwarp = bid * 32 + wid;

    // unit mappings (warp-uniform, static per warp)
    const int qkv_row = gwarp >> 1, qkv_s2 = gwarp & 1;      // valid if gwarp<3072
    const int op_row  = gwarp >> 2, op_s4  = gwarp & 3;      // valid if gwarp<4096
    const int gu_row  = gwarp >> 1, gu_s2  = gwarp & 1;      // first unit, gwarp<4736<5632 always

    // ---- embed + zero first-layer down partials ----
    if (bid == 0) g_hA[tid] = embed[(size_t)input_ids[0] * H + tid];
    if (bid == 1) {
        #pragma unroll
        for (int s = 0; s < 4; s++) g_dp[s][tid] = 0.f;
    }

    // prefetch qkv weights for layer 0 (before the barrier)
    float4 pQ0, pQ1;
    const float* qkvW = nullptr;
    {
        if (gwarp < 2 * (H + 2 * KVH * HD)) {
            if (qkv_row < H)
                qkvW = q_w + (size_t)qkv_row * H;
            else if (qkv_row < H + KVH * HD)
                qkvW = k_w + (size_t)(qkv_row - H) * H;
            else
                qkvW = v_w + (size_t)(qkv_row - H - KVH * HD) * H;
            const float4* w4 = (const float4*)qkvW;
            pQ0 = w4[qkv_s2 * 128 + lane];
            pQ1 = w4[qkv_s2 * 128 + lane + 32];
        }
    }
    grid_sync();

    const int pos = pos_ids[0];
    const int cl = (pos + ACHUNKS) >> 3;

    for (int l = 0; l < LAYERS; l++) {
        // =========== S1: combine h, rms1, qkv (weights prefetched) ===========
        float hv = g_hA[tid] + g_dp[0][tid] + g_dp[1][tid] + g_dp[2][tid] + g_dp[3][tid];
        if (bid == 0) g_hB[tid] = hv;
        xs[tid] = hv * ln1_w[(size_t)l * H + tid];
        float ssq = block_rsum(hv * hv, red);
        float rs = rsqrtf(ssq / (float)H + EPS);

        if (gwarp < 2 * (H + 2 * KVH * HD)) {
            const float4* w4 = (const float4*)qkvW;
            const float4* x4 = (const float4*)xs;
            float4 w2 = w4[qkv_s2 * 128 + lane + 64];
            float4 w3 = w4[qkv_s2 * 128 + lane + 96];
            float s = d4(pQ0, x4[qkv_s2 * 128 + lane])
                    + d4(pQ1, x4[qkv_s2 * 128 + lane + 32])
                    + d4(w2,  x4[qkv_s2 * 128 + lane + 64])
                    + d4(w3,  x4[qkv_s2 * 128 + lane + 96]);
            #pragma unroll
            for (int o = 16; o; o >>= 1) s += __shfl_xor_sync(~0u, s, o);
            if (lane == 0) g_qkvp[qkv_s2][qkv_row] = s * rs;
        }
        grid_sync();

        // =========== S2: attention (flash-decode, 128 blocks) ===========
        if (bid < NH * ACHUNKS) {
            int head = bid >> 3, ch = bid & (ACHUNKS - 1), kvh = head >> 2;
            int j0 = ch * cl;
            int j1 = min(j0 + cl, pos + 1);
            int n = j1 - j0;

            if (tid < HD) {
                float c  = cosc[(size_t)pos * HD + tid];
                float sn = sinc[(size_t)pos * HD + tid];
                int qi = head * HD + tid;
                float q0 = g_qkvp[0][qi] + g_qkvp[1][qi];
                int qr_i = head * HD + ((tid < HD / 2) ? tid + HD / 2 : tid - HD / 2);
                float qr = g_qkvp[0][qr_i] + g_qkvp[1][qr_i];
                if (tid < HD / 2) qr = -qr;
                qs[tid] = q0 * c + qr * sn;

                int ki = H + kvh * HD + tid;
                float k0 = g_qkvp[0][ki] + g_qkvp[1][ki];
                int kr_i = H + kvh * HD + ((tid < HD / 2) ? tid + HD / 2 : tid - HD / 2);
                float kr = g_qkvp[0][kr_i] + g_qkvp[1][kr_i];
                if (tid < HD / 2) kr = -kr;
                kn[tid] = k0 * c + kr * sn;

                int vi = H + KVH * HD + kvh * HD + tid;
                vn[tid] = g_qkvp[0][vi] + g_qkvp[1][vi];
            }
            __syncthreads();

            const float* K = kv + (size_t)l * KVH * CTX * HD + (size_t)kvh * CTX * HD;
            const float* V = kv + (size_t)(LAYERS + l) * KVH * CTX * HD + (size_t)kvh * CTX * HD;
            const float4* q4 = (const float4*)qs;

            int half = lane >> 4, hl = lane & 15;
            for (int jb = j0 + wid * 2; jb < j1; jb += 64) {
                int j = jb + half;
                bool valid = (j < j1);
                const float4* k4;
                if (!valid)           k4 = (const float4*)kn;
                else if (j == pos)    k4 = (const float4*)kn;
                else                  k4 = (const float4*)(K + (size_t)j * HD);
                float4 a = q4[hl], b = k4[hl];
                float s = a.x * b.x + a.y * b.y + a.z * b.z + a.w * b.w;
                #pragma unroll
                for (int o = 8; o; o >>= 1) s += __shfl_xor_sync(~0u, s, o);
                if (hl == 0 && valid) sc[j - j0] = s * 0.125f;
            }
            __syncthreads();

            float m = -1e30f;
            if (tid < n) m = sc[tid];
            float M = block_rmax(m, red);

            float e = 0.f;
            if (tid < n) {
                e = __expf(sc[tid] - M);
                sc[tid] = e;
            }
            float S = block_rsum(e, red);

            float a0 = 0.f, a1 = 0.f;
            for (int j = j0 + wid; j < j1; j += 32) {
                float p = sc[j - j0];
                const float* Vr = (j == pos) ? (const float*)vn : V + (size_t)j * HD;
                a0 += p * Vr[lane];
                a1 += p * Vr[lane + 32];
            }
            part[wid][lane]      = a0;
            part[wid][lane + 32] = a1;
            __syncthreads();
            if (tid == 0) { g_am[head][ch] = (n > 0) ? M : -1e30f; g_as[head][ch] = S; }
            if (tid < HD) {
                float t = 0.f;
                #pragma unroll
                for (int w = 0; w < 32; w++) t += part[w][tid];
                g_ao[head][ch][tid] = t;
            }
        }
        // prefetch o-proj weights (full 2 float4) before barrier
        float4 pO0, pO1;
        const float4* opW = (const float4*)(o_w + (size_t)l * H * H + (size_t)op_row * H);
        if (gwarp < 4 * H) {
            pO0 = opW[op_s4 * 64 + lane];
            pO1 = opW[op_s4 * 64 + lane + 32];
        }
        grid_sync();

        // =========== S3: combine attention, o-proj (prefetched) ===========
        {
            int head = tid >> 6, d = tid & (HD - 1);
            float M = -1e30f;
            #pragma unroll
            for (int c = 0; c < ACHUNKS; c++) M = fmaxf(M, g_am[head][c]);
            float S = 0.f, o = 0.f;
            #pragma unroll
            for (int c = 0; c < ACHUNKS; c++) {
                float e = __expf(g_am[head][c] - M);
                S += g_as[head][c] * e;
                o += g_ao[head][c][d] * e;
            }
            xs[tid] = o / S;
        }
        __syncthreads();

        if (gwarp < 4 * H) {
            const float4* x4 = (const float4*)xs;
            float s = d4(pO0, x4[op_s4 * 64 + lane]) + d4(pO1, x4[op_s4 * 64 + lane + 32]);
            #pragma unroll
            for (int o = 16; o; o >>= 1) s += __shfl_xor_sync(~0u, s, o);
            if (lane == 0) g_op[op_s4][op_row] = s;
        }
        // prefetch gate weights (full 4 float4) before barrier
        float4 pG0, pG1, pG2, pG3;
        const float4* gW = (const float4*)(gate_w + (size_t)l * INTER * H + (size_t)gu_row * H);
        {
            pG0 = gW[gu_s2 * 128 + lane];
            pG1 = gW[gu_s2 * 128 + lane + 32];
            pG2 = gW[gu_s2 * 128 + lane + 64];
            pG3 = gW[gu_s2 * 128 + lane + 96];
        }
        grid_sync();

        // =========== S4: combine h, rms2, gate(prefetched)+up ===========
        hv = g_hB[tid] + g_op[0][tid] + g_op[1][tid] + g_op[2][tid] + g_op[3][tid];
        if (bid == 0) g_hA[tid] = hv;
        xs[tid] = hv * ln2_w[(size_t)l * H + tid];
        ssq = block_rsum(hv * hv, red);
        rs = rsqrtf(ssq / (float)H + EPS);

        {
            const float4* uW = (const float4*)(up_w + (size_t)l * INTER * H + (size_t)gu_row * H);
            const float4* x4 = (const float4*)xs;
            float4 a0 = x4[gu_s2 * 128 + lane];
            float4 a1 = x4[gu_s2 * 128 + lane + 32];
            float4 a2 = x4[gu_s2 * 128 + lane + 64];
            float4 a3 = x4[gu_s2 * 128 + lane + 96];
            float sg = d4(pG0, a0) + d4(pG1, a1) + d4(pG2, a2) + d4(pG3, a3);
            float su = d4(uW[gu_s2 * 128 + lane], a0)
                     + d4(uW[gu_s2 * 128 + lane + 32], a1)
                     + d4(uW[gu_s2 * 128 + lane + 64], a2)
                     + d4(uW[gu_s2 * 128 + lane + 96], a3);
            #pragma unroll
            for (int o = 16; o; o >>= 1) {
                sg += __shfl_xor_sync(~0u, sg, o);
                su += __shfl_xor_sync(~0u, su, o);
            }
            if (lane == 0) { g_gp[gu_s2][gu_row] = sg * rs; g_upp[gu_s2][gu_row] = su * rs; }
        }
        // second unit for warps 0..895 (unit gwarp + 4736)
        if (gwarp < 2 * INTER - NWARPS) {
            int u = gwarp + NWARPS;
            int r = u >> 1, s2 = u & 1;
            const float4* Wg = (const float4*)(gate_w + (size_t)l * INTER * H + (size_t)r * H);
            const float4* Wu = (const float4*)(up_w   + (size_t)l * INTER * H + (size_t)r * H);
            const float4* x4 = (const float4*)xs;
            float sg = 0.f, su = 0.f;
            #pragma unroll
            for (int k = 0; k < 4; k++) {
                int i = s2 * 128 + lane + k * 32;
                float4 wg = Wg[i], wu = Wu[i], a = x4[i];
                sg += d4(wg, a);
                su += d4(wu, a);
            }
            #pragma unroll
            for (int o = 16; o; o >>= 1) {
                sg += __shfl_xor_sync(~0u, sg, o);
                su += __shfl_xor_sync(~0u, su, o);
            }
            if (lane == 0) { g_gp[s2][r] = sg * rs; g_upp[s2][r] = su * rs; }
        }
        // prefetch down weights (3 of 5.5 float4) before barrier
        float4 pD0, pD1, pD2;
        const float4* dW = (const float4*)(down_w + (size_t)l * H * INTER
                                           + (size_t)op_row * INTER + (size_t)op_s4 * 704);
        if (gwarp < 4 * H) {
            pD0 = dW[lane];
            pD1 = dW[lane + 32];
            pD2 = dW[lane + 64];
        }
        grid_sync();

        // =========== S5: combine gact -> smem, down (partly prefetched) ===========
        for (int i = tid; i < INTER; i += 1024) {
            float g = g_gp[0][i] + g_gp[1][i];
            float u = g_upp[0][i] + g_upp[1][i];
            xm[i] = (g / (1.f + __expf(-g))) * u;
        }
        __syncthreads();

        if (gwarp < 4 * H) {
            const float4* x4 = (const float4*)(xm + op_s4 * 704);
            float s = d4(pD0, x4[lane]) + d4(pD1, x4[lane + 32]) + d4(pD2, x4[lane + 64]);
            float4 w3 = dW[lane + 96], w4v = dW[lane + 128];
            s += d4(w3, x4[lane + 96]) + d4(w4v, x4[lane + 128]);
            if (lane < 16) {
                float4 w5 = dW[lane + 160];
                s += d4(w5, x4[lane + 160]);
            }
            #pragma unroll
            for (int o = 16; o; o >>= 1) s += __shfl_xor_sync(~0u, s, o);
            if (lane == 0) g_dp[op_s4][op_row] = s;
        }
        // prefetch next layer's qkv before barrier
        if (l + 1 < LAYERS && gwarp < 2 * (H + 2 * KVH * HD)) {
            if (qkv_row < H)
                qkvW = q_w + (size_t)(l + 1) * H * H + (size_t)qkv_row * H;
            else if (qkv_row < H + KVH * HD)
                qkvW = k_w + (size_t)(l + 1) * (KVH * HD) * H + (size_t)(qkv_row - H) * H;
            else
                qkvW = v_w + (size_t)(l + 1) * (KVH * HD) * H + (size_t)(qkv_row - H - KVH * HD) * H;
            const float4* w4 = (const float4*)qkvW;
            pQ0 = w4[qkv_s2 * 128 + lane];
            pQ1 = w4[qkv_s2 * 128 + lane + 32];
        }
        grid_sync();
    }

    // =========== final norm + lm_head (pairwise rows) + argmax ===========
    float hv = g_hA[tid] + g_dp[0][tid] + g_dp[1][tid] + g_dp[2][tid] + g_dp[3][tid];
    xs[tid] = hv * norm_w[tid];
    float ssq = block_rsum(hv * hv, red);
    float rsf = rsqrtf(ssq / (float)H + EPS);

    float bv = -1e30f;
    int   bi = 0x7fffffff;
    {
        const float4* x4 = (const float4*)xs;
        for (int r = gwarp; r < VOCAB; r += 2 * NWARPS) {
            int r2 = r + NWARPS;
            bool v2 = (r2 < VOCAB);
            const float4* w0 = (const float4*)(lm_head + (size_t)r * H);
            const float4* w1 = (const float4*)(lm_head + (size_t)(v2 ? r2 : r) * H);
            float s0 = 0.f, s1 = 0.f;
            #pragma unroll
            for (int k = 0; k < 8; k++) {
                int i = lane + k * 32;
                float4 a = x4[i];
                s0 += d4(w0[i], a);
                s1 += d4(w1[i], a);
            }
            #pragma unroll
            for (int o = 16; o; o >>= 1) {
                s0 += __shfl_xor_sync(~0u, s0, o);
                s1 += __shfl_xor_sync(~0u, s1, o);
            }
            s0 *= rsf; s1 *= rsf;
            if (s0 > bv) { bv = s0; bi = r; }
            if (v2 && s1 > bv) { bv = s1; bi = r2; }
        }
    }
    if (lane == 0) { red[wid] = bv; redi[wid] = bi; }
    __syncthreads();
    if (tid == 0) {
        float b = red[0]; int ii = redi[0];
        #pragma unroll
        for (int i = 1; i < 32; i++)
            if (red[i] > b || (red[i] == b && redi[i] < ii)) { b = red[i]; ii = redi[i]; }
        g_lmv[bid] = b;
        g_lmi[bid] = ii;
    }
    grid_sync();
    if (bid == 0 && tid == 0) {
        float b = g_lmv[0]; int ii = g_lmi[0];
        for (int i = 1; i < NBLOCKS; i++) {
            float v = g_lmv[i]; int id = g_lmi[i];
            if (v > b || (v == b && id < ii)) { b = v; ii = id; }
        }
        out[0] = (float)ii;
        out[1] = b;
    }
}

// ---------------------------------------------------------------------------
extern "C" void kernel_launch(void* const* d_in, const int* in_sizes, int n_in,
                              void* d_out, int out_size) {
    const float* embed   = (const float*)d_in[0];
    const float* q_w     = (const float*)d_in[1];
    const float* k_w     = (const float*)d_in[2];
    const float* v_w     = (const float*)d_in[3];
    const float* o_w     = (const float*)d_in[4];
    const float* gate_w  = (const float*)d_in[5];
    const float* up_w    = (const float*)d_in[6];
    const float* down_w  = (const float*)d_in[7];
    const float* ln1_w   = (const float*)d_in[8];
    const float* ln2_w   = (const float*)d_in[9];
    const float* norm_w  = (const float*)d_in[10];
    const float* lm_head = (const float*)d_in[11];
    const float* kv      = (const float*)d_in[12];
    const float* cosc    = (const float*)d_in[13];
    const float* sinc    = (const float*)d_in[14];
    const int* input_ids = (const int*)d_in[17];
    const int* pos_ids   = (const int*)d_in[18];

    decode_k<<<NBLOCKS, 1024>>>(embed, q_w, k_w, v_w, o_w, gate_w, up_w, down_w,
                                ln1_w, ln2_w, norm_w, lm_head, kv, cosc, sinc,
                                input_ids, pos_ids, (float*)d_out);
}

// round 7
// speedup vs baseline: 1.1207x; 1.0542x over previous
#include <cuda_runtime.h>
#include <math.h>
#include <stdint.h>

#define LAYERS 8
#define H      1024
#define NH     16
#define KVH    4
#define HD     64
#define INTER  2816
#define VOCAB  32000
#define CTX    2048
#define EPS    1e-5f

#define NBLOCKS 148
#define ACHUNKS 8
#define QKV_R   (H + 2 * KVH * HD)     // 1536
#define GU_R    (2 * INTER)            // 5632
#define QOFFS   20480                  // float offset of second slab region (80KB)
#define LMTILE  20                     // lm_head rows per tile (80KB)
#define SMEM_FLOATS (6416 + 40960)     // 189504 bytes

// ---------------------------------------------------------------------------
__device__ __align__(16) float g_hid[H];
__device__ __align__(16) float g_qkv[QKV_R];
__device__ __align__(16) float g_gu[GU_R];
__device__ float g_am[NH][ACHUNKS];
__device__ float g_as[NH][ACHUNKS];
__device__ __align__(16) float g_ao[NH][ACHUNKS][HD];
__device__ float    g_lmv[NBLOCKS];
__device__ int      g_lmi[NBLOCKS];
__device__ unsigned g_barcnt;
__device__ unsigned g_bargen;

// ---------------------------------------------------------------------------
__device__ __forceinline__ uint32_t s2u(const void* p) {
    return (uint32_t)__cvta_generic_to_shared(p);
}

__device__ __forceinline__ void mbar_init(uint32_t mb) {
    asm volatile("mbarrier.init.shared.b64 [%0], %1;" :: "r"(mb), "r"(1u) : "memory");
}
__device__ __forceinline__ void mbar_expect(uint32_t mb, uint32_t bytes) {
    asm volatile("mbarrier.arrive.expect_tx.shared.b64 _, [%0], %1;"
                 :: "r"(mb), "r"(bytes) : "memory");
}
__device__ __forceinline__ void mbar_wait(uint32_t mb, unsigned parity) {
    asm volatile(
        "{\n\t.reg .pred P;\n\t"
        "LAB_W%=:\n\t"
        "mbarrier.try_wait.parity.acquire.cta.shared::cta.b64 P, [%0], %1, 0x989680;\n\t"
        "@P bra LAB_D%=;\n\t"
        "bra LAB_W%=;\n\t"
        "LAB_D%=:\n\t}"
        :: "r"(mb), "r"(parity) : "memory");
}
// chunked 1D bulk copy global->shared, completion to mbar
__device__ __forceinline__ void issue_chunks(uint32_t dst, const float* src,
                                             uint32_t bytes, uint32_t mb) {
    while (bytes) {
        uint32_t c = bytes > 32768u ? 32768u : bytes;
        asm volatile(
            "cp.async.bulk.shared::cluster.global.mbarrier::complete_tx::bytes [%0], [%1], %2, [%3];"
            :: "r"(dst), "l"(src), "r"(c), "r"(mb) : "memory");
        dst += c; src += c / 4; bytes -= c;
    }
}

// ---------------------------------------------------------------------------
__device__ __forceinline__ void grid_sync() {
    __syncthreads();
    if (threadIdx.x == 0) {
        __threadfence();
        unsigned gen = *(volatile unsigned*)&g_bargen;
        if (atomicAdd(&g_barcnt, 1u) == NBLOCKS - 1) {
            g_barcnt = 0;
            __threadfence();
            atomicAdd(&g_bargen, 1u);
        } else {
            while (*(volatile unsigned*)&g_bargen == gen) { }
            __threadfence();
        }
    }
    __syncthreads();
}

__device__ __forceinline__ float block_rsum(float v, float* red) {
    int lane = threadIdx.x & 31, wid = threadIdx.x >> 5;
    #pragma unroll
    for (int o = 16; o; o >>= 1) v += __shfl_xor_sync(~0u, v, o);
    if (lane == 0) red[wid] = v;
    __syncthreads();
    if (threadIdx.x == 0) {
        float t = 0.f;
        #pragma unroll
        for (int i = 0; i < 32; i++) t += red[i];
        red[0] = t;
    }
    __syncthreads();
    float r = red[0];
    __syncthreads();
    return r;
}

__device__ __forceinline__ float block_rmax(float v, float* red) {
    int lane = threadIdx.x & 31, wid = threadIdx.x >> 5;
    #pragma unroll
    for (int o = 16; o; o >>= 1) v = fmaxf(v, __shfl_xor_sync(~0u, v, o));
    if (lane == 0) red[wid] = v;
    __syncthreads();
    if (threadIdx.x == 0) {
        float t = red[0];
        #pragma unroll
        for (int i = 1; i < 32; i++) t = fmaxf(t, red[i]);
        red[0] = t;
    }
    __syncthreads();
    float r = red[0];
    __syncthreads();
    return r;
}

__device__ __forceinline__ float d4(float4 w, float4 a) {
    return w.x * a.x + w.y * a.y + w.z * a.z + w.w * a.w;
}

__device__ __forceinline__ float warp_red(float s) {
    #pragma unroll
    for (int o = 16; o; o >>= 1) s += __shfl_xor_sync(~0u, s, o);
    return s;
}

// ---------------------------------------------------------------------------
__global__ void __launch_bounds__(1024, 1)
decode_k(const float* __restrict__ embed,  const float* __restrict__ q_w,
         const float* __restrict__ k_w,    const float* __restrict__ v_w,
         const float* __restrict__ o_w,    const float* __restrict__ gate_w,
         const float* __restrict__ up_w,   const float* __restrict__ down_w,
         const float* __restrict__ ln1_w,  const float* __restrict__ ln2_w,
         const float* __restrict__ norm_w, const float* __restrict__ lm_head,
         const float* __restrict__ kv,     const float* __restrict__ cosc,
         const float* __restrict__ sinc,   const int* __restrict__ input_ids,
         const int* __restrict__ pos_ids,  float* __restrict__ out) {
    extern __shared__ __align__(16) float smem[];
    float* xs   = smem;                       // [1024]
    float* xm   = smem + 1024;                // [2816]
    float* red  = smem + 3840;                // [32]
    int*   redi = (int*)(smem + 3872);        // [32]
    float* sc   = smem + 3904;                // [256]
    float* qs   = smem + 4160;                // [64]
    float* kn   = smem + 4224;                // [64]
    float* vn   = smem + 4288;                // [64]
    float* part = smem + 4352;                // [32][64]
    unsigned long long* mbars = (unsigned long long*)(smem + 6400);
    float* slab = smem + 6416;                // [40960] (160KB)

    const int tid = threadIdx.x, lane = tid & 31, wid = tid >> 5;
    const int bid = blockIdx.x;
    const uint32_t mb0 = s2u(mbars), mb1 = s2u(mbars + 1);
    unsigned pc0 = 0, pc1 = 0;

    // block row ranges
    const int r0q = (QKV_R * bid) / NBLOCKS,  r1q = (QKV_R * (bid + 1)) / NBLOCKS;
    const int r0o = (H * bid) / NBLOCKS,      r1o = (H * (bid + 1)) / NBLOCKS;
    const int r0g = (GU_R * bid) / NBLOCKS,   r1g = (GU_R * (bid + 1)) / NBLOCKS;
    const int r0L = (VOCAB * bid) / NBLOCKS,  r1L = (VOCAB * (bid + 1)) / NBLOCKS;

    if (tid == 0) { mbar_init(mb0); mbar_init(mb1); }
    __syncthreads();
    asm volatile("fence.proxy.async.shared::cta;" ::: "memory");

    // embed + issue layer-0 qkv slab copy
    if (bid == 0) g_hid[tid] = embed[(size_t)input_ids[0] * H + tid];
    if (tid == 0) {
        mbar_expect(mb1, (uint32_t)((r1q - r0q) * H * 4));
        uint32_t dst = s2u(slab + QOFFS);
        int a = r0q, b = (r1q < H) ? r1q : H;
        if (a < b) { issue_chunks(dst, q_w + (size_t)a * H, (b - a) * H * 4, mb1); dst += (b - a) * H * 4; }
        a = (r0q > H) ? r0q : H; b = (r1q < H + 256) ? r1q : H + 256;
        if (a < b) { issue_chunks(dst, k_w + (size_t)(a - H) * H, (b - a) * H * 4, mb1); dst += (b - a) * H * 4; }
        a = (r0q > H + 256) ? r0q : H + 256; b = r1q;
        if (a < b) { issue_chunks(dst, v_w + (size_t)(a - H - 256) * H, (b - a) * H * 4, mb1); }
    }
    grid_sync();

    const int pos = pos_ids[0];
    const int cl = (pos + ACHUNKS) >> 3;

    for (int l = 0; l < LAYERS; l++) {
        // =========== S1: rms1 + qkv (slab @QOFFS, copy in flight) ===========
        float hv = g_hid[tid];
        xs[tid] = hv * ln1_w[(size_t)l * H + tid];
        float ssq = block_rsum(hv * hv, red);
        float rs = rsqrtf(ssq / (float)H + EPS);

        mbar_wait(mb1, pc1 & 1); pc1++;
        for (int r = r0q + wid; r < r1q; r += 32) {
            const float4* w4 = (const float4*)(slab + QOFFS + (size_t)(r - r0q) * H);
            const float4* x4 = (const float4*)xs;
            float s = 0.f;
            #pragma unroll
            for (int k = 0; k < 8; k++) { int i = lane + k * 32; s += d4(w4[i], x4[i]); }
            s = warp_red(s);
            if (lane == 0) g_qkv[r] = s * rs;
        }
        grid_sync();

        // =========== S2: issue o-slab copy, then attention ===========
        if (tid == 0) {
            mbar_expect(mb0, (uint32_t)((r1o - r0o) * H * 4));
            issue_chunks(s2u(slab), o_w + (size_t)l * H * H + (size_t)r0o * H,
                         (r1o - r0o) * H * 4, mb0);
        }
        if (bid < NH * ACHUNKS) {
            int head = bid >> 3, ch = bid & (ACHUNKS - 1), kvh = head >> 2;
            int j0 = ch * cl;
            int j1 = min(j0 + cl, pos + 1);
            int n = j1 - j0;

            if (tid < HD) {
                float c  = cosc[(size_t)pos * HD + tid];
                float sn = sinc[(size_t)pos * HD + tid];
                float q0 = g_qkv[head * HD + tid];
                float qr = g_qkv[head * HD + ((tid < HD / 2) ? tid + HD / 2 : tid - HD / 2)];
                if (tid < HD / 2) qr = -qr;
                qs[tid] = q0 * c + qr * sn;
                float k0 = g_qkv[H + kvh * HD + tid];
                float kr = g_qkv[H + kvh * HD + ((tid < HD / 2) ? tid + HD / 2 : tid - HD / 2)];
                if (tid < HD / 2) kr = -kr;
                kn[tid] = k0 * c + kr * sn;
                vn[tid] = g_qkv[H + KVH * HD + kvh * HD + tid];
            }
            __syncthreads();

            const float* K = kv + (size_t)l * KVH * CTX * HD + (size_t)kvh * CTX * HD;
            const float* V = kv + (size_t)(LAYERS + l) * KVH * CTX * HD + (size_t)kvh * CTX * HD;
            const float4* q4 = (const float4*)qs;

            int half = lane >> 4, hl = lane & 15;
            for (int jb = j0 + wid * 2; jb < j1; jb += 64) {
                int j = jb + half;
                bool valid = (j < j1);
                const float4* k4;
                if (!valid)        k4 = (const float4*)kn;
                else if (j == pos) k4 = (const float4*)kn;
                else               k4 = (const float4*)(K + (size_t)j * HD);
                float4 a = q4[hl], b = k4[hl];
                float s = a.x * b.x + a.y * b.y + a.z * b.z + a.w * b.w;
                #pragma unroll
                for (int o = 8; o; o >>= 1) s += __shfl_xor_sync(~0u, s, o);
                if (hl == 0 && valid) sc[j - j0] = s * 0.125f;
            }
            __syncthreads();

            float m = -1e30f;
            if (tid < n) m = sc[tid];
            float M = block_rmax(m, red);
            float e = 0.f;
            if (tid < n) { e = __expf(sc[tid] - M); sc[tid] = e; }
            float S = block_rsum(e, red);

            float a0 = 0.f, a1 = 0.f;
            for (int j = j0 + wid; j < j1; j += 32) {
                float p = sc[j - j0];
                const float* Vr = (j == pos) ? (const float*)vn : V + (size_t)j * HD;
                a0 += p * Vr[lane];
                a1 += p * Vr[lane + 32];
            }
            part[wid * HD + lane]      = a0;
            part[wid * HD + lane + 32] = a1;
            __syncthreads();
            if (tid == 0) { g_am[head][ch] = (n > 0) ? M : -1e30f; g_as[head][ch] = S; }
            if (tid < HD) {
                float t = 0.f;
                #pragma unroll
                for (int w = 0; w < 32; w++) t += part[w * HD + tid];
                g_ao[head][ch][tid] = t;
            }
        }
        grid_sync();

        // =========== S3: combine attention -> xs, o-proj rows ===========
        {
            int head = tid >> 6, d = tid & (HD - 1);
            float M = -1e30f;
            #pragma unroll
            for (int c = 0; c < ACHUNKS; c++) M = fmaxf(M, g_am[head][c]);
            float S = 0.f, o = 0.f;
            #pragma unroll
            for (int c = 0; c < ACHUNKS; c++) {
                float e = __expf(g_am[head][c] - M);
                S += g_as[head][c] * e;
                o += g_ao[head][c][d] * e;
            }
            xs[tid] = o / S;
        }
        __syncthreads();

        mbar_wait(mb0, pc0 & 1); pc0++;
        for (int r = r0o + wid; r < r1o; r += 32) {
            const float4* w4 = (const float4*)(slab + (size_t)(r - r0o) * H);
            const float4* x4 = (const float4*)xs;
            float s = 0.f;
            #pragma unroll
            for (int k = 0; k < 8; k++) { int i = lane + k * 32; s += d4(w4[i], x4[i]); }
            s = warp_red(s);
            if (lane == 0) g_hid[r] += s;
        }
        grid_sync();

        // =========== S4: issue gate+up copy, rms2, gate+up rows ===========
        if (tid == 0) {
            mbar_expect(mb0, (uint32_t)((r1g - r0g) * H * 4));
            uint32_t dst = s2u(slab);
            int a = r0g, b = (r1g < INTER) ? r1g : INTER;
            if (a < b) {
                issue_chunks(dst, gate_w + (size_t)l * INTER * H + (size_t)a * H,
                             (b - a) * H * 4, mb0);
                dst += (b - a) * H * 4;
            }
            a = (r0g > INTER) ? r0g : INTER; b = r1g;
            if (a < b) {
                issue_chunks(dst, up_w + (size_t)l * INTER * H + (size_t)(a - INTER) * H,
                             (b - a) * H * 4, mb0);
            }
        }
        hv = g_hid[tid];
        xs[tid] = hv * ln2_w[(size_t)l * H + tid];
        ssq = block_rsum(hv * hv, red);
        float rs2 = rsqrtf(ssq / (float)H + EPS);

        mbar_wait(mb0, pc0 & 1); pc0++;
        for (int r = r0g + wid; r < r1g; r += 32) {
            const float4* w4 = (const float4*)(slab + (size_t)(r - r0g) * H);
            const float4* x4 = (const float4*)xs;
            float s = 0.f;
            #pragma unroll
            for (int k = 0; k < 8; k++) { int i = lane + k * 32; s += d4(w4[i], x4[i]); }
            s = warp_red(s);
            if (lane == 0) g_gu[r] = s * rs2;
        }
        grid_sync();

        // =========== S5: issue down copy, build xm, down rows (+next qkv) ===========
        if (tid == 0) {
            mbar_expect(mb0, (uint32_t)((r1o - r0o) * INTER * 4));
            issue_chunks(s2u(slab), down_w + (size_t)l * H * INTER + (size_t)r0o * INTER,
                         (r1o - r0o) * INTER * 4, mb0);
        }
        for (int i = tid; i < INTER; i += 1024) {
            float g = g_gu[i];
            float u = g_gu[INTER + i];
            xm[i] = (g / (1.f + __expf(-g))) * u;
        }
        __syncthreads();

        mbar_wait(mb0, pc0 & 1); pc0++;
        if (tid == 0 && l + 1 < LAYERS) {
            // prefetch next layer's qkv into QOFFS region (overlaps down compute)
            mbar_expect(mb1, (uint32_t)((r1q - r0q) * H * 4));
            uint32_t dst = s2u(slab + QOFFS);
            int a = r0q, b = (r1q < H) ? r1q : H;
            if (a < b) { issue_chunks(dst, q_w + (size_t)(l + 1) * H * H + (size_t)a * H, (b - a) * H * 4, mb1); dst += (b - a) * H * 4; }
            a = (r0q > H) ? r0q : H; b = (r1q < H + 256) ? r1q : H + 256;
            if (a < b) { issue_chunks(dst, k_w + (size_t)(l + 1) * 256 * H + (size_t)(a - H) * H, (b - a) * H * 4, mb1); dst += (b - a) * H * 4; }
            a = (r0q > H + 256) ? r0q : H + 256; b = r1q;
            if (a < b) { issue_chunks(dst, v_w + (size_t)(l + 1) * 256 * H + (size_t)(a - H - 256) * H, (b - a) * H * 4, mb1); }
        }
        for (int r = r0o + wid; r < r1o; r += 32) {
            const float4* w4 = (const float4*)(slab + (size_t)(r - r0o) * INTER);
            const float4* x4 = (const float4*)xm;
            float s = 0.f;
            for (int i = lane; i < INTER / 4; i += 32) s += d4(w4[i], x4[i]);
            s = warp_red(s);
            if (lane == 0) g_hid[r] += s;
        }
        grid_sync();
    }

    // =========== final norm + lm_head (double-buffered tiles) + argmax ===========
    {
        int nt = (r1L - r0L + LMTILE - 1) / LMTILE;
        // issue tile 0 into buf0 (mb0)
        if (tid == 0) {
            int a = r0L, b = min(r0L + LMTILE, r1L);
            mbar_expect(mb0, (uint32_t)((b - a) * H * 4));
            issue_chunks(s2u(slab), lm_head + (size_t)a * H, (b - a) * H * 4, mb0);
        }
        float hv = g_hid[tid];
        xs[tid] = hv * norm_w[tid];
        float ssq = block_rsum(hv * hv, red);
        float rsf = rsqrtf(ssq / (float)H + EPS);

        float bv = -1e30f;
        int   bi = 0x7fffffff;
        const float4* x4 = (const float4*)xs;

        for (int t = 0; t < nt; t++) {
            if (t & 1) { mbar_wait(mb1, pc1 & 1); pc1++; }
            else       { mbar_wait(mb0, pc0 & 1); pc0++; }
            if (tid == 0 && t + 1 < nt) {
                int a = r0L + (t + 1) * LMTILE, b = min(a + LMTILE, r1L);
                uint32_t mb = ((t + 1) & 1) ? mb1 : mb0;
                mbar_expect(mb, (uint32_t)((b - a) * H * 4));
                issue_chunks(s2u(slab + (((t + 1) & 1) ? QOFFS : 0)),
                             lm_head + (size_t)a * H, (b - a) * H * 4, mb);
            }
            int a = r0L + t * LMTILE, b = min(a + LMTILE, r1L);
            const float* buf = slab + ((t & 1) ? QOFFS : 0);
            for (int r = a + wid; r < b; r += 32) {
                const float4* w4 = (const float4*)(buf + (size_t)(r - a) * H);
                float s = 0.f;
                #pragma unroll
                for (int k = 0; k < 8; k++) { int i = lane + k * 32; s += d4(w4[i], x4[i]); }
                s = warp_red(s) * rsf;
                if (s > bv || (s == bv && r < bi)) { bv = s; bi = r; }
            }
            __syncthreads();
        }

        if (lane == 0) { red[wid] = bv; redi[wid] = bi; }
        __syncthreads();
        if (tid == 0) {
            float b = red[0]; int ii = redi[0];
            #pragma unroll
            for (int i = 1; i < 32; i++)
                if (red[i] > b || (red[i] == b && redi[i] < ii)) { b = red[i]; ii = redi[i]; }
            g_lmv[bid] = b;
            g_lmi[bid] = ii;
        }
        grid_sync();
        if (bid == 0 && tid == 0) {
            float b = g_lmv[0]; int ii = g_lmi[0];
            for (int i = 1; i < NBLOCKS; i++) {
                float v = g_lmv[i]; int id = g_lmi[i];
                if (v > b || (v == b && id < ii)) { b = v; ii = id; }
            }
            out[0] = (float)ii;
            out[1] = b;
        }
    }
}

// ---------------------------------------------------------------------------
extern "C" void kernel_launch(void* const* d_in, const int* in_sizes, int n_in,
                              void* d_out, int out_size) {
    const float* embed   = (const float*)d_in[0];
    const float* q_w     = (const float*)d_in[1];
    const float* k_w     = (const float*)d_in[2];
    const float* v_w     = (const float*)d_in[3];
    const float* o_w     = (const float*)d_in[4];
    const float* gate_w  = (const float*)d_in[5];
    const float* up_w    = (const float*)d_in[6];
    const float* down_w  = (const float*)d_in[7];
    const float* ln1_w   = (const float*)d_in[8];
    const float* ln2_w   = (const float*)d_in[9];
    const float* norm_w  = (const float*)d_in[10];
    const float* lm_head = (const float*)d_in[11];
    const float* kv      = (const float*)d_in[12];
    const float* cosc    = (const float*)d_in[13];
    const float* sinc    = (const float*)d_in[14];
    const int* input_ids = (const int*)d_in[17];
    const int* pos_ids   = (const int*)d_in[18];

    static bool attr_set = false;
    if (!attr_set) {
        cudaFuncSetAttribute(decode_k, cudaFuncAttributeMaxDynamicSharedMemorySize,
                             SMEM_FLOATS * 4);
        attr_set = true;
    }

    decode_k<<<NBLOCKS, 1024, SMEM_FLOATS * 4>>>(
        embed, q_w, k_w, v_w, o_w, gate_w, up_w, down_w,
        ln1_w, ln2_w, norm_w, lm_head, kv, cosc, sinc,
        input_ids, pos_ids, (float*)d_out);
}